// round 12
// baseline (speedup 1.0000x reference)
#include <cuda_runtime.h>
#include <cuda_bf16.h>
#include <cstdint>
#include <cstddef>

#define B_  4
#define T_  2048
#define C_  1024
#define H_  16
#define HS  64
#define BT  (B_ * T_)        // 8192
#define FF  (4 * C_)         // 4096

// ======================= helpers ===========================================
__device__ __forceinline__ float tf32r(float x) {
    uint32_t u;
    asm("cvt.rna.tf32.f32 %0, %1;" : "=r"(u) : "f"(x));
    return __uint_as_float(u);
}
__device__ __forceinline__ uint32_t smem_u32(const void* p) {
    uint32_t a;
    asm("{ .reg .u64 t; cvta.to.shared.u64 t, %1; cvt.u32.u64 %0, t; }" : "=r"(a) : "l"(p));
    return a;
}
__device__ __forceinline__ void cp16(uint32_t dst, const void* src) {
    asm volatile("cp.async.cg.shared.global [%0], [%1], 16;" :: "r"(dst), "l"(src));
}
#define CP_COMMIT() asm volatile("cp.async.commit_group;" ::: "memory")
#define CP_WAIT1()  asm volatile("cp.async.wait_group 1;" ::: "memory")
#define CP_WAIT0()  asm volatile("cp.async.wait_group 0;" ::: "memory")

__device__ __forceinline__ void mma_tf32(float* d, const uint32_t* a, const uint32_t* b) {
    asm volatile(
        "mma.sync.aligned.m16n8k8.row.col.f32.tf32.tf32.f32 "
        "{%0,%1,%2,%3}, {%4,%5,%6,%7}, {%8,%9}, {%0,%1,%2,%3};"
        : "+f"(d[0]), "+f"(d[1]), "+f"(d[2]), "+f"(d[3])
        : "r"(a[0]), "r"(a[1]), "r"(a[2]), "r"(a[3]), "r"(b[0]), "r"(b[1]));
}

// ======================= scratch ===========================================
__device__ float g_xn  [BT * C_];
__device__ float g_qkv [3 * BT * C_];      // [3][B][H][T][hs], tf32-rounded
__device__ float g_att [BT * C_];
__device__ float g_x1  [BT * C_];
__device__ float g_xn2 [BT * C_];
__device__ float g_h   [BT * FF];
__device__ float g_wqkv[C_ * 3 * C_];
__device__ float g_wo  [C_ * C_];
__device__ float g_w1  [C_ * FF];
__device__ float g_w2  [FF * C_];

// ======================= fused weight prep =================================
__global__ void prep_kernel(const float* __restrict__ Wq, const float* __restrict__ Wk,
                            const float* __restrict__ Wv, const float* __restrict__ Wo,
                            const float* __restrict__ W1, const float* __restrict__ W2,
                            float* __restrict__ wqkv, float* __restrict__ wo,
                            float* __restrict__ w1, float* __restrict__ w2) {
    int idx = blockIdx.x * blockDim.x + threadIdx.x;
    const int NQ = 3 * C_ * C_ / 4;
    const int NO = C_ * C_ / 4;
    const int N1 = C_ * FF / 4;
    if (idx < NQ) {
        int n4row = 3 * C_ / 4;
        int k = idx / n4row;
        int n = (idx - k * n4row) * 4;
        int which = n >> 10, h = (n >> 6) & 15, d = n & 63;
        const float* W = (which == 0) ? Wq : (which == 1) ? Wk : Wv;
        float4 v = *(const float4*)&W[((size_t)h * C_ + k) * HS + d];
        v.x = tf32r(v.x); v.y = tf32r(v.y); v.z = tf32r(v.z); v.w = tf32r(v.w);
        *(float4*)&wqkv[(size_t)k * (3 * C_) + n] = v;
        return;
    }
    idx -= NQ;
    const float* src; float* dst;
    if (idx < NO)              { src = Wo; dst = wo; }
    else if ((idx -= NO) < N1) { src = W1; dst = w1; }
    else                       { idx -= N1; src = W2; dst = w2; }
    float4 v = ((const float4*)src)[idx];
    v.x = tf32r(v.x); v.y = tf32r(v.y); v.z = tf32r(v.z); v.w = tf32r(v.w);
    ((float4*)dst)[idx] = v;
}

// ======================= LayerNorm =========================================
__global__ void ln_kernel(const float* __restrict__ x,
                          const float* __restrict__ g,
                          const float* __restrict__ b,
                          float* __restrict__ out) {
    int row = blockIdx.x;
    int tid = threadIdx.x;
    const float4* xr = (const float4*)(x + (size_t)row * C_);
    float4 xv = xr[tid];
    float s  = xv.x + xv.y + xv.z + xv.w;
    float ss = xv.x * xv.x + xv.y * xv.y + xv.z * xv.z + xv.w * xv.w;
    #pragma unroll
    for (int o = 16; o > 0; o >>= 1) {
        s  += __shfl_xor_sync(0xffffffffu, s,  o);
        ss += __shfl_xor_sync(0xffffffffu, ss, o);
    }
    __shared__ float sb[8], sb2[8];
    int wid = tid >> 5, lid = tid & 31;
    if (lid == 0) { sb[wid] = s; sb2[wid] = ss; }
    __syncthreads();
    float tot = 0.f, tot2 = 0.f;
    #pragma unroll
    for (int i = 0; i < 8; i++) { tot += sb[i]; tot2 += sb2[i]; }
    float mean = tot * (1.0f / C_);
    float var  = tot2 * (1.0f / C_) - mean * mean;
    float rstd = rsqrtf(var + 1e-5f);
    float4 gv = ((const float4*)g)[tid];
    float4 bv = ((const float4*)b)[tid];
    float4 ov;
    ov.x = tf32r((xv.x - mean) * rstd * gv.x + bv.x);
    ov.y = tf32r((xv.y - mean) * rstd * gv.y + bv.y);
    ov.z = tf32r((xv.z - mean) * rstd * gv.z + bv.z);
    ov.w = tf32r((xv.w - mean) * rstd * gv.w + bv.w);
    ((float4*)(out + (size_t)row * C_))[tid] = ov;
}

// =============== TF32 GEMM A: 128x256, 8 warps 64x64 (R9 proven) ===========
static constexpr int BM = 128, BN = 256, BK = 32;
static constexpr int APAD = 36;
static constexpr int BPAD = 264;
static constexpr int ABYTES = BM * APAD * 4;
static constexpr int BBYTES = BK * BPAD * 4;
static constexpr int STAGE_BYTES = ABYTES + BBYTES;
static constexpr int NSTAGES = 3;
static constexpr int MM_SMEM = NSTAGES * STAGE_BYTES;

template<int EPI>
__global__ __launch_bounds__(256, 1)
void mm_kernel(const float* __restrict__ A, const float* __restrict__ Bw,
               const float* __restrict__ bias, const float* __restrict__ res,
               float* __restrict__ Cout, int K, int N) {
    extern __shared__ __align__(16) char dsm[];
    const uint32_t smem0 = smem_u32(dsm);
    const int tid  = threadIdx.x;
    const int wid  = tid >> 5;
    const int lane = tid & 31;
    const int m0 = blockIdx.y * BM;
    const int n0 = blockIdx.x * BN;
    const int nch = K >> 5;

    const int warpM = wid >> 2;
    const int warpN = wid & 3;

    const int arow0 = tid >> 3;
    const int acb   = (tid & 7) << 4;
    const int brow  = tid >> 3;
    const int bc0   = (tid & 7) << 4;

    float acc[4][8][4];
    #pragma unroll
    for (int mt = 0; mt < 4; mt++)
        #pragma unroll
        for (int nt = 0; nt < 8; nt++)
            #pragma unroll
            for (int r = 0; r < 4; r++) acc[mt][nt][r] = 0.f;

    auto load_stage = [&](int st, int kpos) {
        uint32_t sa  = smem0 + st * STAGE_BYTES;
        uint32_t sbm = sa + ABYTES;
        #pragma unroll
        for (int j = 0; j < 4; j++) {
            int r = arow0 + j * 32;
            cp16(sa + r * (APAD * 4) + acb,
                 A + (size_t)(m0 + r) * K + kpos + (acb >> 2));
        }
        const float* brp = Bw + (size_t)(kpos + brow) * N + n0;
        #pragma unroll
        for (int j = 0; j < 8; j++) {
            int cb = bc0 + j * 128;
            cp16(sbm + brow * (BPAD * 4) + cb, brp + (cb >> 2));
        }
    };

    load_stage(0, 0); CP_COMMIT();
    load_stage(1, 32); CP_COMMIT();

    const int fr = lane >> 2;
    const int fc = lane & 3;

    uint32_t afr[2][4][4];
    uint32_t bfr[2][8][2];

    auto load_frags = [&](const float* Asm, const float* Bsm, int kk, int buf) {
        const int km = kk * 8 + fc;
        #pragma unroll
        for (int mt = 0; mt < 4; mt++) {
            const int mr = warpM * 64 + mt * 16 + fr;
            afr[buf][mt][0] = __float_as_uint(Asm[mr * APAD + km]);
            afr[buf][mt][1] = __float_as_uint(Asm[(mr + 8) * APAD + km]);
            afr[buf][mt][2] = __float_as_uint(Asm[mr * APAD + km + 4]);
            afr[buf][mt][3] = __float_as_uint(Asm[(mr + 8) * APAD + km + 4]);
        }
        #pragma unroll
        for (int nt = 0; nt < 8; nt++) {
            const int nc = warpN * 64 + nt * 8 + fr;
            bfr[buf][nt][0] = __float_as_uint(Bsm[km * BPAD + nc]);
            bfr[buf][nt][1] = __float_as_uint(Bsm[(km + 4) * BPAD + nc]);
        }
    };

    for (int kc = 0; kc < nch; kc++) {
        CP_WAIT1();
        __syncthreads();
        if (kc + 2 < nch) load_stage((kc + 2) % NSTAGES, (kc + 2) * 32);
        CP_COMMIT();

        const float* Asm = (const float*)(dsm + (kc % NSTAGES) * STAGE_BYTES);
        const float* Bsm = (const float*)((const char*)Asm + ABYTES);

        load_frags(Asm, Bsm, 0, 0);
        #pragma unroll
        for (int kk = 0; kk < 4; kk++) {
            const int cur = kk & 1;
            if (kk < 3) load_frags(Asm, Bsm, kk + 1, cur ^ 1);
            #pragma unroll
            for (int mt = 0; mt < 4; mt++)
                #pragma unroll
                for (int nt = 0; nt < 8; nt++)
                    mma_tf32(acc[mt][nt], afr[cur][mt], bfr[cur][nt]);
        }
    }

    #pragma unroll
    for (int mt = 0; mt < 4; mt++) {
        #pragma unroll
        for (int half = 0; half < 2; half++) {
            const int m = m0 + warpM * 64 + mt * 16 + fr + half * 8;
            #pragma unroll
            for (int nt = 0; nt < 8; nt++) {
                const int n = n0 + warpN * 64 + nt * 8 + 2 * fc;
                float2 v = make_float2(acc[mt][nt][half * 2], acc[mt][nt][half * 2 + 1]);
                if (EPI == 0) {
                    v.x = tf32r(v.x); v.y = tf32r(v.y);
                    const int which = n >> 10;
                    if (which == 0) { v.x *= 0.125f; v.y *= 0.125f; }
                    const int b = m >> 11, t = m & 2047;
                    const int h = (n >> 6) & 15, d = n & 63;
                    *(float2*)&Cout[((((size_t)which * B_ + b) * H_ + h) * T_ + t) * HS + d] = v;
                } else {
                    const float2 bb = *(const float2*)&bias[n];
                    v.x += bb.x; v.y += bb.y;
                    if (EPI == 1) {
                        float2 rr = *(const float2*)&res[(size_t)m * N + n];
                        v.x += rr.x; v.y += rr.y;
                    } else {
                        v.x = tf32r(fmaxf(v.x, 0.f));
                        v.y = tf32r(fmaxf(v.y, 0.f));
                    }
                    *(float2*)&Cout[(size_t)m * N + n] = v;
                }
            }
        }
    }
}

// ====== TF32 GEMM B: 128x128, 8 warps 64x32, 2 CTAs/SM (Wo / FF2) ==========
static constexpr int BMs = 128, BNs = 128;
static constexpr int BPADs = 136;
static constexpr int ABYTESs = BMs * APAD * 4;              // 18432
static constexpr int BBYTESs = BK * BPADs * 4;              // 17408
static constexpr int STAGEs = ABYTESs + BBYTESs;            // 35840
static constexpr int MM_SMEMs = NSTAGES * STAGEs;           // 107520

__global__ __launch_bounds__(256, 2)
void mm_sm_kernel(const float* __restrict__ A, const float* __restrict__ Bw,
                  const float* __restrict__ bias, const float* __restrict__ res,
                  float* __restrict__ Cout, int K, int N) {
    extern __shared__ __align__(16) char dsm[];
    const uint32_t smem0 = smem_u32(dsm);
    const int tid  = threadIdx.x;
    const int wid  = tid >> 5;
    const int lane = tid & 31;
    const int m0 = blockIdx.y * BMs;
    const int n0 = blockIdx.x * BNs;
    const int nch = K >> 5;

    const int warpM = wid >> 2;
    const int warpN = wid & 3;

    const int arow0 = tid >> 3;
    const int acb   = (tid & 7) << 4;
    const int brow  = tid >> 3;
    const int bc0   = (tid & 7) << 4;

    float acc[4][4][4];
    #pragma unroll
    for (int mt = 0; mt < 4; mt++)
        #pragma unroll
        for (int nt = 0; nt < 4; nt++)
            #pragma unroll
            for (int r = 0; r < 4; r++) acc[mt][nt][r] = 0.f;

    auto load_stage = [&](int st, int kpos) {
        uint32_t sa  = smem0 + st * STAGEs;
        uint32_t sbm = sa + ABYTESs;
        #pragma unroll
        for (int j = 0; j < 4; j++) {
            int r = arow0 + j * 32;
            cp16(sa + r * (APAD * 4) + acb,
                 A + (size_t)(m0 + r) * K + kpos + (acb >> 2));
        }
        const float* brp = Bw + (size_t)(kpos + brow) * N + n0;
        #pragma unroll
        for (int j = 0; j < 4; j++) {
            int cb = bc0 + j * 128;
            cp16(sbm + brow * (BPADs * 4) + cb, brp + (cb >> 2));
        }
    };

    load_stage(0, 0); CP_COMMIT();
    load_stage(1, 32); CP_COMMIT();

    const int fr = lane >> 2;
    const int fc = lane & 3;

    for (int kc = 0; kc < nch; kc++) {
        CP_WAIT1();
        __syncthreads();
        if (kc + 2 < nch) load_stage((kc + 2) % NSTAGES, (kc + 2) * 32);
        CP_COMMIT();

        const float* Asm = (const float*)(dsm + (kc % NSTAGES) * STAGEs);
        const float* Bsm = (const float*)((const char*)Asm + ABYTESs);

        #pragma unroll
        for (int kk = 0; kk < 4; kk++) {
            const int km = kk * 8 + fc;
            uint32_t afr[4][4];
            #pragma unroll
            for (int mt = 0; mt < 4; mt++) {
                const int mr = warpM * 64 + mt * 16 + fr;
                afr[mt][0] = __float_as_uint(Asm[mr * APAD + km]);
                afr[mt][1] = __float_as_uint(Asm[(mr + 8) * APAD + km]);
                afr[mt][2] = __float_as_uint(Asm[mr * APAD + km + 4]);
                afr[mt][3] = __float_as_uint(Asm[(mr + 8) * APAD + km + 4]);
            }
            uint32_t bfr[4][2];
            #pragma unroll
            for (int nt = 0; nt < 4; nt++) {
                const int nc = warpN * 32 + nt * 8 + fr;
                bfr[nt][0] = __float_as_uint(Bsm[km * BPADs + nc]);
                bfr[nt][1] = __float_as_uint(Bsm[(km + 4) * BPADs + nc]);
            }
            #pragma unroll
            for (int mt = 0; mt < 4; mt++)
                #pragma unroll
                for (int nt = 0; nt < 4; nt++)
                    mma_tf32(acc[mt][nt], afr[mt], bfr[nt]);
        }
    }

    // epilogue: +bias +res
    #pragma unroll
    for (int mt = 0; mt < 4; mt++) {
        #pragma unroll
        for (int half = 0; half < 2; half++) {
            const int m = m0 + warpM * 64 + mt * 16 + fr + half * 8;
            #pragma unroll
            for (int nt = 0; nt < 4; nt++) {
                const int n = n0 + warpN * 32 + nt * 8 + 2 * fc;
                float2 v = make_float2(acc[mt][nt][half * 2], acc[mt][nt][half * 2 + 1]);
                const float2 bb = *(const float2*)&bias[n];
                float2 rr = *(const float2*)&res[(size_t)m * N + n];
                v.x += bb.x + rr.x; v.y += bb.y + rr.y;
                *(float2*)&Cout[(size_t)m * N + n] = v;
            }
        }
    }
}

// ======================= tensor-core causal flash attention ================
// 2 CTAs/SM; 32-key tiles, DOUBLE-buffered K/V (same smem as 64 single).
static constexpr int KP = 68;
static constexpr int VP = 72;
static constexpr int PP = 36;
static constexpr int QP = 68;
static constexpr int QS_FL = 128 * QP;       // 8704
static constexpr int KS_FL = 32 * KP;        // 2176 per stage
static constexpr int VS_FL = 32 * VP;        // 2304 per stage
static constexpr int AT_SMEM = (QS_FL + 2 * KS_FL + 2 * VS_FL + 128 * PP) * 4; // 89088

__global__ __launch_bounds__(256, 2)
void attn_kernel(const float* __restrict__ Q,
                 const float* __restrict__ K,
                 const float* __restrict__ V,
                 float* __restrict__ out) {
    const int bh = blockIdx.y;
    const int q0 = ((int)gridDim.x - 1 - (int)blockIdx.x) * 128;
    const int tid = threadIdx.x, w = tid >> 5, lane = tid & 31;
    const int qw = q0 + w * 16;
    const int r = lane >> 2, c = lane & 3;

    extern __shared__ __align__(16) float sm[];
    float* Qs  = sm;                                // [128][QP]
    float* Ksm = sm + QS_FL;                        // [2][32][KP]
    float* Vsm = sm + QS_FL + 2 * KS_FL;            // [2][32][VP]
    float* Ps  = sm + QS_FL + 2 * KS_FL + 2 * VS_FL;// [128][PP]

    const float* Kbh = K + (size_t)bh * T_ * HS;
    const float* Vbh = V + (size_t)bh * T_ * HS;

    // ---- Q tile load (own cp.async group) --------------------------------
    {
        const float4* qp = (const float4*)(Q + ((size_t)bh * T_ + q0) * HS);
        for (int i = tid; i < 128 * 16; i += 256) {
            int row = i >> 4, c4 = i & 15;
            cp16(smem_u32(&Qs[row * QP + c4 * 4]), &qp[i]);
        }
        CP_COMMIT();
    }

    auto load_kv = [&](int tile, int st) {
        const float4* kp = (const float4*)(Kbh + (size_t)(tile * 32) * HS);
        const float4* vp = (const float4*)(Vbh + (size_t)(tile * 32) * HS);
        float* kd = Ksm + st * KS_FL;
        float* vd = Vsm + st * VS_FL;
        for (int i = tid; i < 32 * 16; i += 256) {
            int row = i >> 4, c4 = i & 15;
            cp16(smem_u32(&kd[row * KP + c4 * 4]), &kp[i]);
            cp16(smem_u32(&vd[row * VP + c4 * 4]), &vp[i]);
        }
        CP_COMMIT();
    };

    const int ntiles = (q0 >> 5) + 4;
    load_kv(0, 0);
    load_kv(1, 1);

    float o[8][4];
    #pragma unroll
    for (int nt = 0; nt < 8; nt++)
        #pragma unroll
        for (int j = 0; j < 4; j++) o[nt][j] = 0.f;
    float m0 = -1e30f, m1 = -1e30f, l0 = 0.f, l1 = 0.f;

    const float* qbase0 = &Qs[(w * 16 + r) * QP + c];
    const float* qbase1 = qbase0 + 8 * QP;

    for (int t = 0; t < ntiles; t++) {
        if (t + 1 < ntiles) CP_WAIT1(); else CP_WAIT0();
        __syncthreads();               // tile t (and Q on t=0) visible

        const int k0 = t * 32;
        const float* Kst = Ksm + (t & 1) * KS_FL;
        const float* Vst = Vsm + (t & 1) * VS_FL;

        // ---- S = Q @ K^T ----
        float s[4][4];
        #pragma unroll
        for (int nt = 0; nt < 4; nt++)
            #pragma unroll
            for (int j = 0; j < 4; j++) s[nt][j] = 0.f;
        #pragma unroll
        for (int kc = 0; kc < 8; kc++) {
            uint32_t aq[4];
            aq[0] = __float_as_uint(qbase0[kc * 8]);
            aq[1] = __float_as_uint(qbase1[kc * 8]);
            aq[2] = __float_as_uint(qbase0[kc * 8 + 4]);
            aq[3] = __float_as_uint(qbase1[kc * 8 + 4]);
            #pragma unroll
            for (int nt = 0; nt < 4; nt++) {
                uint32_t bfr[2];
                bfr[0] = __float_as_uint(Kst[(nt * 8 + r) * KP + kc * 8 + c]);
                bfr[1] = __float_as_uint(Kst[(nt * 8 + r) * KP + kc * 8 + c + 4]);
                mma_tf32(s[nt], aq, bfr);
            }
        }

        // ---- causal mask ----
        if (k0 + 31 > qw) {
            const int row0 = qw + r, row1 = qw + r + 8;
            #pragma unroll
            for (int nt = 0; nt < 4; nt++) {
                const int key = k0 + nt * 8 + 2 * c;
                if (key     > row0) s[nt][0] = -1e30f;
                if (key + 1 > row0) s[nt][1] = -1e30f;
                if (key     > row1) s[nt][2] = -1e30f;
                if (key + 1 > row1) s[nt][3] = -1e30f;
            }
        }

        // ---- online softmax ----
        float mx0 = m0, mx1 = m1;
        #pragma unroll
        for (int nt = 0; nt < 4; nt++) {
            mx0 = fmaxf(mx0, fmaxf(s[nt][0], s[nt][1]));
            mx1 = fmaxf(mx1, fmaxf(s[nt][2], s[nt][3]));
        }
        mx0 = fmaxf(mx0, __shfl_xor_sync(0xffffffffu, mx0, 1));
        mx0 = fmaxf(mx0, __shfl_xor_sync(0xffffffffu, mx0, 2));
        mx1 = fmaxf(mx1, __shfl_xor_sync(0xffffffffu, mx1, 1));
        mx1 = fmaxf(mx1, __shfl_xor_sync(0xffffffffu, mx1, 2));
        const float corr0 = __expf(m0 - mx0);
        const float corr1 = __expf(m1 - mx1);
        m0 = mx0; m1 = mx1;

        __syncwarp();
        float ls0 = 0.f, ls1 = 0.f;
        float* prow0 = &Ps[(w * 16 + r) * PP];
        float* prow1 = &Ps[(w * 16 + r + 8) * PP];
        #pragma unroll
        for (int nt = 0; nt < 4; nt++) {
            float p0 = tf32r(__expf(s[nt][0] - mx0));
            float p1 = tf32r(__expf(s[nt][1] - mx0));
            float p2 = tf32r(__expf(s[nt][2] - mx1));
            float p3 = tf32r(__expf(s[nt][3] - mx1));
            ls0 += p0 + p1; ls1 += p2 + p3;
            *(float2*)&prow0[nt * 8 + 2 * c] = make_float2(p0, p1);
            *(float2*)&prow1[nt * 8 + 2 * c] = make_float2(p2, p3);
        }
        ls0 += __shfl_xor_sync(0xffffffffu, ls0, 1);
        ls0 += __shfl_xor_sync(0xffffffffu, ls0, 2);
        ls1 += __shfl_xor_sync(0xffffffffu, ls1, 1);
        ls1 += __shfl_xor_sync(0xffffffffu, ls1, 2);
        l0 = l0 * corr0 + ls0;
        l1 = l1 * corr1 + ls1;

        #pragma unroll
        for (int nt = 0; nt < 8; nt++) {
            o[nt][0] *= corr0; o[nt][1] *= corr0;
            o[nt][2] *= corr1; o[nt][3] *= corr1;
        }
        __syncwarp();

        // ---- O += P @ V  (32 keys = 4 kc blocks) ----
        #pragma unroll
        for (int kc = 0; kc < 4; kc++) {
            uint32_t afr[4];
            afr[0] = __float_as_uint(prow0[kc * 8 + c]);
            afr[1] = __float_as_uint(prow1[kc * 8 + c]);
            afr[2] = __float_as_uint(prow0[kc * 8 + c + 4]);
            afr[3] = __float_as_uint(prow1[kc * 8 + c + 4]);
            #pragma unroll
            for (int nt = 0; nt < 8; nt++) {
                uint32_t bfr[2];
                bfr[0] = __float_as_uint(Vst[(kc * 8 + c) * VP + nt * 8 + r]);
                bfr[1] = __float_as_uint(Vst[(kc * 8 + c + 4) * VP + nt * 8 + r]);
                mma_tf32(o[nt], afr, bfr);
            }
        }

        __syncthreads();               // all warps done with buffer (t&1)
        if (t + 2 < ntiles) load_kv(t + 2, t & 1);
    }

    const float inv0 = 1.0f / l0, inv1 = 1.0f / l1;
    const int b = bh >> 4, h = bh & 15;
    float* ob0 = out + ((size_t)(b * T_ + qw + r)) * C_ + h * HS;
    float* ob1 = out + ((size_t)(b * T_ + qw + r + 8)) * C_ + h * HS;
    #pragma unroll
    for (int nt = 0; nt < 8; nt++) {
        *(float2*)&ob0[nt * 8 + 2 * c] =
            make_float2(tf32r(o[nt][0] * inv0), tf32r(o[nt][1] * inv0));
        *(float2*)&ob1[nt * 8 + 2 * c] =
            make_float2(tf32r(o[nt][2] * inv1), tf32r(o[nt][3] * inv1));
    }
}

// ===========================================================================
extern "C" void kernel_launch(void* const* d_in, const int* in_sizes, int n_in,
                              void* d_out, int out_size) {
    const float* x   = (const float*)d_in[0];
    const float* Wq  = (const float*)d_in[1];
    const float* Wk  = (const float*)d_in[2];
    const float* Wv  = (const float*)d_in[3];
    const float* Wo  = (const float*)d_in[4];
    const float* bo  = (const float*)d_in[5];
    const float* g1  = (const float*)d_in[6];
    const float* be1 = (const float*)d_in[7];
    const float* g2  = (const float*)d_in[8];
    const float* be2 = (const float*)d_in[9];
    const float* W1  = (const float*)d_in[10];
    const float* b1  = (const float*)d_in[11];
    const float* W2  = (const float*)d_in[12];
    const float* b2  = (const float*)d_in[13];
    float* out = (float*)d_out;

    float *xn, *qkv, *att, *x1, *xn2, *h, *wqkv, *wo, *w1, *w2;
    cudaGetSymbolAddress((void**)&xn,   g_xn);
    cudaGetSymbolAddress((void**)&qkv,  g_qkv);
    cudaGetSymbolAddress((void**)&att,  g_att);
    cudaGetSymbolAddress((void**)&x1,   g_x1);
    cudaGetSymbolAddress((void**)&xn2,  g_xn2);
    cudaGetSymbolAddress((void**)&h,    g_h);
    cudaGetSymbolAddress((void**)&wqkv, g_wqkv);
    cudaGetSymbolAddress((void**)&wo,   g_wo);
    cudaGetSymbolAddress((void**)&w1,   g_w1);
    cudaGetSymbolAddress((void**)&w2,   g_w2);

    cudaFuncSetAttribute(mm_kernel<0>, cudaFuncAttributeMaxDynamicSharedMemorySize, MM_SMEM);
    cudaFuncSetAttribute(mm_kernel<2>, cudaFuncAttributeMaxDynamicSharedMemorySize, MM_SMEM);
    cudaFuncSetAttribute(mm_sm_kernel, cudaFuncAttributeMaxDynamicSharedMemorySize, MM_SMEMs);
    cudaFuncSetAttribute(attn_kernel,  cudaFuncAttributeMaxDynamicSharedMemorySize, AT_SMEM);

    prep_kernel<<<(3 * C_ * C_ + C_ * C_ + 2 * C_ * FF) / 4 / 256, 256>>>(
        Wq, Wk, Wv, Wo, W1, W2, wqkv, wo, w1, w2);

    // 1) ln1
    ln_kernel<<<BT, 256>>>(x, g1, be1, xn);
    // 2) fused QKV GEMM -> scatter [3,B,H,T,hs] (q pre-scaled by 1/8)
    mm_kernel<0><<<dim3(3 * C_ / BN, BT / BM), 256, MM_SMEM>>>(xn, wqkv, nullptr, nullptr, qkv, C_, 3 * C_);
    // 3) tensor-core flash attention (2 CTAs/SM, 32-key dbl-buffered tiles)
    attn_kernel<<<dim3(T_ / 128, B_ * H_), 256, AT_SMEM>>>(
        qkv, qkv + (size_t)BT * C_, qkv + 2 * (size_t)BT * C_, att);
    // 4) x1 = x + att @ Wo + bo   (small-N kernel, 2 CTAs/SM)
    mm_sm_kernel<<<dim3(C_ / BNs, BT / BMs), 256, MM_SMEMs>>>(att, wo, bo, x, x1, C_, C_);
    // 5) ln2
    ln_kernel<<<BT, 256>>>(x1, g2, be2, xn2);
    // 6) h = relu(xn2 @ W1 + b1)
    mm_kernel<2><<<dim3(FF / BN, BT / BM), 256, MM_SMEM>>>(xn2, w1, b1, nullptr, h, C_, FF);
    // 7) out = x1 + h @ W2 + b2   (small-N kernel, 2 CTAs/SM)
    mm_sm_kernel<<<dim3(C_ / BNs, BT / BMs), 256, MM_SMEMs>>>(h, w2, b2, x1, out, FF, C_);
}

// round 15
// speedup vs baseline: 1.6046x; 1.6046x over previous
#include <cuda_runtime.h>
#include <cuda_bf16.h>
#include <cstdint>
#include <cstddef>

#define B_  4
#define T_  2048
#define C_  1024
#define H_  16
#define HS  64
#define BT  (B_ * T_)        // 8192
#define FF  (4 * C_)         // 4096

// ======================= helpers ===========================================
__device__ __forceinline__ float tf32r(float x) {
    uint32_t u;
    asm("cvt.rna.tf32.f32 %0, %1;" : "=r"(u) : "f"(x));
    return __uint_as_float(u);
}
__device__ __forceinline__ uint32_t smem_u32(const void* p) {
    uint32_t a;
    asm("{ .reg .u64 t; cvta.to.shared.u64 t, %1; cvt.u32.u64 %0, t; }" : "=r"(a) : "l"(p));
    return a;
}
__device__ __forceinline__ void cp16(uint32_t dst, const void* src) {
    asm volatile("cp.async.cg.shared.global [%0], [%1], 16;" :: "r"(dst), "l"(src));
}
#define CP_COMMIT() asm volatile("cp.async.commit_group;" ::: "memory")
#define CP_WAIT1()  asm volatile("cp.async.wait_group 1;" ::: "memory")
#define CP_WAIT0()  asm volatile("cp.async.wait_group 0;" ::: "memory")

__device__ __forceinline__ void mma_tf32(float* d, const uint32_t* a, const uint32_t* b) {
    asm volatile(
        "mma.sync.aligned.m16n8k8.row.col.f32.tf32.tf32.f32 "
        "{%0,%1,%2,%3}, {%4,%5,%6,%7}, {%8,%9}, {%0,%1,%2,%3};"
        : "+f"(d[0]), "+f"(d[1]), "+f"(d[2]), "+f"(d[3])
        : "r"(a[0]), "r"(a[1]), "r"(a[2]), "r"(a[3]), "r"(b[0]), "r"(b[1]));
}

// ======================= scratch ===========================================
__device__ float g_xn  [BT * C_];
__device__ float g_qkv [3 * BT * C_];      // [3][B][H][T][hs], tf32-rounded
__device__ float g_att [BT * C_];
__device__ float g_x1  [BT * C_];
__device__ float g_xn2 [BT * C_];
__device__ float g_h   [BT * FF];
__device__ float g_wqkv[C_ * 3 * C_];
__device__ float g_wo  [C_ * C_];
__device__ float g_w1  [C_ * FF];
__device__ float g_w2  [FF * C_];

// ======================= fused weight prep =================================
__global__ void prep_kernel(const float* __restrict__ Wq, const float* __restrict__ Wk,
                            const float* __restrict__ Wv, const float* __restrict__ Wo,
                            const float* __restrict__ W1, const float* __restrict__ W2,
                            float* __restrict__ wqkv, float* __restrict__ wo,
                            float* __restrict__ w1, float* __restrict__ w2) {
    int idx = blockIdx.x * blockDim.x + threadIdx.x;
    const int NQ = 3 * C_ * C_ / 4;
    const int NO = C_ * C_ / 4;
    const int N1 = C_ * FF / 4;
    if (idx < NQ) {
        int n4row = 3 * C_ / 4;
        int k = idx / n4row;
        int n = (idx - k * n4row) * 4;
        int which = n >> 10, h = (n >> 6) & 15, d = n & 63;
        const float* W = (which == 0) ? Wq : (which == 1) ? Wk : Wv;
        float4 v = *(const float4*)&W[((size_t)h * C_ + k) * HS + d];
        v.x = tf32r(v.x); v.y = tf32r(v.y); v.z = tf32r(v.z); v.w = tf32r(v.w);
        *(float4*)&wqkv[(size_t)k * (3 * C_) + n] = v;
        return;
    }
    idx -= NQ;
    const float* src; float* dst;
    if (idx < NO)              { src = Wo; dst = wo; }
    else if ((idx -= NO) < N1) { src = W1; dst = w1; }
    else                       { idx -= N1; src = W2; dst = w2; }
    float4 v = ((const float4*)src)[idx];
    v.x = tf32r(v.x); v.y = tf32r(v.y); v.z = tf32r(v.z); v.w = tf32r(v.w);
    ((float4*)dst)[idx] = v;
}

// ======================= LayerNorm =========================================
__global__ void ln_kernel(const float* __restrict__ x,
                          const float* __restrict__ g,
                          const float* __restrict__ b,
                          float* __restrict__ out) {
    int row = blockIdx.x;
    int tid = threadIdx.x;
    const float4* xr = (const float4*)(x + (size_t)row * C_);
    float4 xv = xr[tid];
    float s  = xv.x + xv.y + xv.z + xv.w;
    float ss = xv.x * xv.x + xv.y * xv.y + xv.z * xv.z + xv.w * xv.w;
    #pragma unroll
    for (int o = 16; o > 0; o >>= 1) {
        s  += __shfl_xor_sync(0xffffffffu, s,  o);
        ss += __shfl_xor_sync(0xffffffffu, ss, o);
    }
    __shared__ float sb[8], sb2[8];
    int wid = tid >> 5, lid = tid & 31;
    if (lid == 0) { sb[wid] = s; sb2[wid] = ss; }
    __syncthreads();
    float tot = 0.f, tot2 = 0.f;
    #pragma unroll
    for (int i = 0; i < 8; i++) { tot += sb[i]; tot2 += sb2[i]; }
    float mean = tot * (1.0f / C_);
    float var  = tot2 * (1.0f / C_) - mean * mean;
    float rstd = rsqrtf(var + 1e-5f);
    float4 gv = ((const float4*)g)[tid];
    float4 bv = ((const float4*)b)[tid];
    float4 ov;
    ov.x = tf32r((xv.x - mean) * rstd * gv.x + bv.x);
    ov.y = tf32r((xv.y - mean) * rstd * gv.y + bv.y);
    ov.z = tf32r((xv.z - mean) * rstd * gv.z + bv.z);
    ov.w = tf32r((xv.w - mean) * rstd * gv.w + bv.w);
    ((float4*)(out + (size_t)row * C_))[tid] = ov;
}

// ======================= TF32 mma.sync GEMM (R9 proven, all 4 GEMMs) =======
static constexpr int BM = 128, BN = 256, BK = 32;
static constexpr int APAD = 36;
static constexpr int BPAD = 264;
static constexpr int ABYTES = BM * APAD * 4;
static constexpr int BBYTES = BK * BPAD * 4;
static constexpr int STAGE_BYTES = ABYTES + BBYTES;
static constexpr int NSTAGES = 3;
static constexpr int MM_SMEM = NSTAGES * STAGE_BYTES;

template<int EPI>
__global__ __launch_bounds__(256, 1)
void mm_kernel(const float* __restrict__ A, const float* __restrict__ Bw,
               const float* __restrict__ bias, const float* __restrict__ res,
               float* __restrict__ Cout, int K, int N) {
    extern __shared__ __align__(16) char dsm[];
    const uint32_t smem0 = smem_u32(dsm);
    const int tid  = threadIdx.x;
    const int wid  = tid >> 5;
    const int lane = tid & 31;
    const int m0 = blockIdx.y * BM;
    const int n0 = blockIdx.x * BN;
    const int nch = K >> 5;

    const int warpM = wid >> 2;
    const int warpN = wid & 3;

    const int arow0 = tid >> 3;
    const int acb   = (tid & 7) << 4;
    const int brow  = tid >> 3;
    const int bc0   = (tid & 7) << 4;

    float acc[4][8][4];
    #pragma unroll
    for (int mt = 0; mt < 4; mt++)
        #pragma unroll
        for (int nt = 0; nt < 8; nt++)
            #pragma unroll
            for (int r = 0; r < 4; r++) acc[mt][nt][r] = 0.f;

    auto load_stage = [&](int st, int kpos) {
        uint32_t sa  = smem0 + st * STAGE_BYTES;
        uint32_t sbm = sa + ABYTES;
        #pragma unroll
        for (int j = 0; j < 4; j++) {
            int r = arow0 + j * 32;
            cp16(sa + r * (APAD * 4) + acb,
                 A + (size_t)(m0 + r) * K + kpos + (acb >> 2));
        }
        const float* brp = Bw + (size_t)(kpos + brow) * N + n0;
        #pragma unroll
        for (int j = 0; j < 8; j++) {
            int cb = bc0 + j * 128;
            cp16(sbm + brow * (BPAD * 4) + cb, brp + (cb >> 2));
        }
    };

    load_stage(0, 0); CP_COMMIT();
    load_stage(1, 32); CP_COMMIT();

    const int fr = lane >> 2;
    const int fc = lane & 3;

    uint32_t afr[2][4][4];
    uint32_t bfr[2][8][2];

    auto load_frags = [&](const float* Asm, const float* Bsm, int kk, int buf) {
        const int km = kk * 8 + fc;
        #pragma unroll
        for (int mt = 0; mt < 4; mt++) {
            const int mr = warpM * 64 + mt * 16 + fr;
            afr[buf][mt][0] = __float_as_uint(Asm[mr * APAD + km]);
            afr[buf][mt][1] = __float_as_uint(Asm[(mr + 8) * APAD + km]);
            afr[buf][mt][2] = __float_as_uint(Asm[mr * APAD + km + 4]);
            afr[buf][mt][3] = __float_as_uint(Asm[(mr + 8) * APAD + km + 4]);
        }
        #pragma unroll
        for (int nt = 0; nt < 8; nt++) {
            const int nc = warpN * 64 + nt * 8 + fr;
            bfr[buf][nt][0] = __float_as_uint(Bsm[km * BPAD + nc]);
            bfr[buf][nt][1] = __float_as_uint(Bsm[(km + 4) * BPAD + nc]);
        }
    };

    for (int kc = 0; kc < nch; kc++) {
        CP_WAIT1();
        __syncthreads();
        if (kc + 2 < nch) load_stage((kc + 2) % NSTAGES, (kc + 2) * 32);
        CP_COMMIT();

        const float* Asm = (const float*)(dsm + (kc % NSTAGES) * STAGE_BYTES);
        const float* Bsm = (const float*)((const char*)Asm + ABYTES);

        load_frags(Asm, Bsm, 0, 0);
        #pragma unroll
        for (int kk = 0; kk < 4; kk++) {
            const int cur = kk & 1;
            if (kk < 3) load_frags(Asm, Bsm, kk + 1, cur ^ 1);
            #pragma unroll
            for (int mt = 0; mt < 4; mt++)
                #pragma unroll
                for (int nt = 0; nt < 8; nt++)
                    mma_tf32(acc[mt][nt], afr[cur][mt], bfr[cur][nt]);
        }
    }

    #pragma unroll
    for (int mt = 0; mt < 4; mt++) {
        #pragma unroll
        for (int half = 0; half < 2; half++) {
            const int m = m0 + warpM * 64 + mt * 16 + fr + half * 8;
            #pragma unroll
            for (int nt = 0; nt < 8; nt++) {
                const int n = n0 + warpN * 64 + nt * 8 + 2 * fc;
                float2 v = make_float2(acc[mt][nt][half * 2], acc[mt][nt][half * 2 + 1]);
                if (EPI == 0) {
                    v.x = tf32r(v.x); v.y = tf32r(v.y);
                    const int which = n >> 10;
                    if (which == 0) { v.x *= 0.125f; v.y *= 0.125f; }
                    const int b = m >> 11, t = m & 2047;
                    const int h = (n >> 6) & 15, d = n & 63;
                    *(float2*)&Cout[((((size_t)which * B_ + b) * H_ + h) * T_ + t) * HS + d] = v;
                } else {
                    const float2 bb = *(const float2*)&bias[n];
                    v.x += bb.x; v.y += bb.y;
                    if (EPI == 1) {
                        float2 rr = *(const float2*)&res[(size_t)m * N + n];
                        v.x += rr.x; v.y += rr.y;
                    } else {
                        v.x = tf32r(fmaxf(v.x, 0.f));
                        v.y = tf32r(fmaxf(v.y, 0.f));
                    }
                    *(float2*)&Cout[(size_t)m * N + n] = v;
                }
            }
        }
    }
}

// ======================= tensor-core causal flash attention ================
// R9 proven config: 2 CTAs/SM, Q in smem (pitch 68), K/V single-buffered
// 64-key tiles, P pitch 68. NEW: fully-masked diagonal tiles skip compute
// (barriers and loads stay outside the guard).
// PITCH RULE: all rows are 64 floats -> pitch >= 64; conflict-free minima
// QP=68, KP=68, VP=72, PP=68. Do not shrink below 64 ever again.
static constexpr int KP = 68;
static constexpr int VP = 72;
static constexpr int PP = 68;
static constexpr int QP = 68;
static constexpr int QS_FL = 128 * QP;
static constexpr int KS_FL = 64 * KP;
static constexpr int VS_FL = 64 * VP;
static constexpr int AT_SMEM = (QS_FL + KS_FL + VS_FL + 128 * PP) * 4;  // 105472

__global__ __launch_bounds__(256, 2)
void attn_kernel(const float* __restrict__ Q,
                 const float* __restrict__ K,
                 const float* __restrict__ V,
                 float* __restrict__ out) {
    const int bh = blockIdx.y;
    const int q0 = ((int)gridDim.x - 1 - (int)blockIdx.x) * 128;
    const int tid = threadIdx.x, w = tid >> 5, lane = tid & 31;
    const int qw = q0 + w * 16;
    const int r = lane >> 2, c = lane & 3;

    extern __shared__ __align__(16) float sm[];
    float* Qs  = sm;                               // [128][QP]
    float* Ksm = sm + QS_FL;                       // [64][KP]
    float* Vsm = sm + QS_FL + KS_FL;               // [64][VP]
    float* Ps  = sm + QS_FL + KS_FL + VS_FL;       // [128][PP]

    const float* Kbh = K + (size_t)bh * T_ * HS;
    const float* Vbh = V + (size_t)bh * T_ * HS;

    // ---- Q tile load (q pre-scaled by 1/8 upstream) ----------------------
    {
        const float4* qp = (const float4*)(Q + ((size_t)bh * T_ + q0) * HS);
        for (int i = tid; i < 128 * 16; i += 256) {
            int row = i >> 4, c4 = i & 15;
            cp16(smem_u32(&Qs[row * QP + c4 * 4]), &qp[i]);
        }
        CP_COMMIT();
    }

    auto load_kv = [&](int tile) {
        const float4* kp = (const float4*)(Kbh + (size_t)(tile * 64) * HS);
        const float4* vp = (const float4*)(Vbh + (size_t)(tile * 64) * HS);
        for (int i = tid; i < 64 * 16; i += 256) {
            int row = i >> 4, c4 = i & 15;
            cp16(smem_u32(&Ksm[row * KP + c4 * 4]), &kp[i]);
            cp16(smem_u32(&Vsm[row * VP + c4 * 4]), &vp[i]);
        }
        CP_COMMIT();
    };

    const int ntiles = (q0 + 128) >> 6;
    load_kv(0);

    float o[8][4];
    #pragma unroll
    for (int nt = 0; nt < 8; nt++)
        #pragma unroll
        for (int j = 0; j < 4; j++) o[nt][j] = 0.f;
    float m0 = -1e30f, m1 = -1e30f, l0 = 0.f, l1 = 0.f;

    const float* qbase0 = &Qs[(w * 16 + r) * QP + c];
    const float* qbase1 = qbase0 + 8 * QP;

    for (int t = 0; t < ntiles; t++) {
        CP_WAIT0();
        __syncthreads();               // K/V (and Q on t=0) visible

        const int k0 = t * 64;
        if (k0 <= qw + 15) {           // skip compute for fully-masked tiles
            // ---- S = Q @ K^T ----
            float s[8][4];
            #pragma unroll
            for (int nt = 0; nt < 8; nt++)
                #pragma unroll
                for (int j = 0; j < 4; j++) s[nt][j] = 0.f;
            #pragma unroll
            for (int kc = 0; kc < 8; kc++) {
                uint32_t aq[4];
                aq[0] = __float_as_uint(qbase0[kc * 8]);
                aq[1] = __float_as_uint(qbase1[kc * 8]);
                aq[2] = __float_as_uint(qbase0[kc * 8 + 4]);
                aq[3] = __float_as_uint(qbase1[kc * 8 + 4]);
                #pragma unroll
                for (int nt = 0; nt < 8; nt++) {
                    uint32_t bfr[2];
                    bfr[0] = __float_as_uint(Ksm[(nt * 8 + r) * KP + kc * 8 + c]);
                    bfr[1] = __float_as_uint(Ksm[(nt * 8 + r) * KP + kc * 8 + c + 4]);
                    mma_tf32(s[nt], aq, bfr);
                }
            }

            // ---- causal mask ----
            if (k0 + 63 > qw) {
                const int row0 = qw + r, row1 = qw + r + 8;
                #pragma unroll
                for (int nt = 0; nt < 8; nt++) {
                    const int key = k0 + nt * 8 + 2 * c;
                    if (key     > row0) s[nt][0] = -1e30f;
                    if (key + 1 > row0) s[nt][1] = -1e30f;
                    if (key     > row1) s[nt][2] = -1e30f;
                    if (key + 1 > row1) s[nt][3] = -1e30f;
                }
            }

            // ---- online softmax ----
            float mx0 = m0, mx1 = m1;
            #pragma unroll
            for (int nt = 0; nt < 8; nt++) {
                mx0 = fmaxf(mx0, fmaxf(s[nt][0], s[nt][1]));
                mx1 = fmaxf(mx1, fmaxf(s[nt][2], s[nt][3]));
            }
            mx0 = fmaxf(mx0, __shfl_xor_sync(0xffffffffu, mx0, 1));
            mx0 = fmaxf(mx0, __shfl_xor_sync(0xffffffffu, mx0, 2));
            mx1 = fmaxf(mx1, __shfl_xor_sync(0xffffffffu, mx1, 1));
            mx1 = fmaxf(mx1, __shfl_xor_sync(0xffffffffu, mx1, 2));
            const float corr0 = __expf(m0 - mx0);
            const float corr1 = __expf(m1 - mx1);
            m0 = mx0; m1 = mx1;

            __syncwarp();
            float ls0 = 0.f, ls1 = 0.f;
            float* prow0 = &Ps[(w * 16 + r) * PP];
            float* prow1 = &Ps[(w * 16 + r + 8) * PP];
            #pragma unroll
            for (int nt = 0; nt < 8; nt++) {
                float p0 = tf32r(__expf(s[nt][0] - mx0));
                float p1 = tf32r(__expf(s[nt][1] - mx0));
                float p2 = tf32r(__expf(s[nt][2] - mx1));
                float p3 = tf32r(__expf(s[nt][3] - mx1));
                ls0 += p0 + p1; ls1 += p2 + p3;
                *(float2*)&prow0[nt * 8 + 2 * c] = make_float2(p0, p1);
                *(float2*)&prow1[nt * 8 + 2 * c] = make_float2(p2, p3);
            }
            ls0 += __shfl_xor_sync(0xffffffffu, ls0, 1);
            ls0 += __shfl_xor_sync(0xffffffffu, ls0, 2);
            ls1 += __shfl_xor_sync(0xffffffffu, ls1, 1);
            ls1 += __shfl_xor_sync(0xffffffffu, ls1, 2);
            l0 = l0 * corr0 + ls0;
            l1 = l1 * corr1 + ls1;

            #pragma unroll
            for (int nt = 0; nt < 8; nt++) {
                o[nt][0] *= corr0; o[nt][1] *= corr0;
                o[nt][2] *= corr1; o[nt][3] *= corr1;
            }
            __syncwarp();

            // ---- O += P @ V ----
            #pragma unroll
            for (int kc = 0; kc < 8; kc++) {
                uint32_t afr[4];
                afr[0] = __float_as_uint(prow0[kc * 8 + c]);
                afr[1] = __float_as_uint(prow1[kc * 8 + c]);
                afr[2] = __float_as_uint(prow0[kc * 8 + c + 4]);
                afr[3] = __float_as_uint(prow1[kc * 8 + c + 4]);
                #pragma unroll
                for (int nt = 0; nt < 8; nt++) {
                    uint32_t bfr[2];
                    bfr[0] = __float_as_uint(Vsm[(kc * 8 + c) * VP + nt * 8 + r]);
                    bfr[1] = __float_as_uint(Vsm[(kc * 8 + c + 4) * VP + nt * 8 + r]);
                    mma_tf32(o[nt], afr, bfr);
                }
            }
        }

        __syncthreads();               // everyone done with K/V before reload
        if (t + 1 < ntiles) load_kv(t + 1);
    }

    const float inv0 = 1.0f / l0, inv1 = 1.0f / l1;
    const int b = bh >> 4, h = bh & 15;
    float* ob0 = out + ((size_t)(b * T_ + qw + r)) * C_ + h * HS;
    float* ob1 = out + ((size_t)(b * T_ + qw + r + 8)) * C_ + h * HS;
    #pragma unroll
    for (int nt = 0; nt < 8; nt++) {
        *(float2*)&ob0[nt * 8 + 2 * c] =
            make_float2(tf32r(o[nt][0] * inv0), tf32r(o[nt][1] * inv0));
        *(float2*)&ob1[nt * 8 + 2 * c] =
            make_float2(tf32r(o[nt][2] * inv1), tf32r(o[nt][3] * inv1));
    }
}

// ===========================================================================
extern "C" void kernel_launch(void* const* d_in, const int* in_sizes, int n_in,
                              void* d_out, int out_size) {
    const float* x   = (const float*)d_in[0];
    const float* Wq  = (const float*)d_in[1];
    const float* Wk  = (const float*)d_in[2];
    const float* Wv  = (const float*)d_in[3];
    const float* Wo  = (const float*)d_in[4];
    const float* bo  = (const float*)d_in[5];
    const float* g1  = (const float*)d_in[6];
    const float* be1 = (const float*)d_in[7];
    const float* g2  = (const float*)d_in[8];
    const float* be2 = (const float*)d_in[9];
    const float* W1  = (const float*)d_in[10];
    const float* b1  = (const float*)d_in[11];
    const float* W2  = (const float*)d_in[12];
    const float* b2  = (const float*)d_in[13];
    float* out = (float*)d_out;

    float *xn, *qkv, *att, *x1, *xn2, *h, *wqkv, *wo, *w1, *w2;
    cudaGetSymbolAddress((void**)&xn,   g_xn);
    cudaGetSymbolAddress((void**)&qkv,  g_qkv);
    cudaGetSymbolAddress((void**)&att,  g_att);
    cudaGetSymbolAddress((void**)&x1,   g_x1);
    cudaGetSymbolAddress((void**)&xn2,  g_xn2);
    cudaGetSymbolAddress((void**)&h,    g_h);
    cudaGetSymbolAddress((void**)&wqkv, g_wqkv);
    cudaGetSymbolAddress((void**)&wo,   g_wo);
    cudaGetSymbolAddress((void**)&w1,   g_w1);
    cudaGetSymbolAddress((void**)&w2,   g_w2);

    cudaFuncSetAttribute(mm_kernel<0>, cudaFuncAttributeMaxDynamicSharedMemorySize, MM_SMEM);
    cudaFuncSetAttribute(mm_kernel<1>, cudaFuncAttributeMaxDynamicSharedMemorySize, MM_SMEM);
    cudaFuncSetAttribute(mm_kernel<2>, cudaFuncAttributeMaxDynamicSharedMemorySize, MM_SMEM);
    cudaFuncSetAttribute(attn_kernel,  cudaFuncAttributeMaxDynamicSharedMemorySize, AT_SMEM);

    prep_kernel<<<(3 * C_ * C_ + C_ * C_ + 2 * C_ * FF) / 4 / 256, 256>>>(
        Wq, Wk, Wv, Wo, W1, W2, wqkv, wo, w1, w2);

    // 1) ln1
    ln_kernel<<<BT, 256>>>(x, g1, be1, xn);
    // 2) fused QKV GEMM -> scatter [3,B,H,T,hs] (q pre-scaled by 1/8)
    mm_kernel<0><<<dim3(3 * C_ / BN, BT / BM), 256, MM_SMEM>>>(xn, wqkv, nullptr, nullptr, qkv, C_, 3 * C_);
    // 3) tensor-core flash attention (2 CTAs/SM)
    attn_kernel<<<dim3(T_ / 128, B_ * H_), 256, AT_SMEM>>>(
        qkv, qkv + (size_t)BT * C_, qkv + 2 * (size_t)BT * C_, att);
    // 4) x1 = x + att @ Wo + bo
    mm_kernel<1><<<dim3(C_ / BN, BT / BM), 256, MM_SMEM>>>(att, wo, bo, x, x1, C_, C_);
    // 5) ln2
    ln_kernel<<<BT, 256>>>(x1, g2, be2, xn2);
    // 6) h = relu(xn2 @ W1 + b1)
    mm_kernel<2><<<dim3(FF / BN, BT / BM), 256, MM_SMEM>>>(xn2, w1, b1, nullptr, h, C_, FF);
    // 7) out = x1 + h @ W2 + b2
    mm_kernel<1><<<dim3(C_ / BN, BT / BM), 256, MM_SMEM>>>(h, w2, b2, x1, out, FF, C_);
}